// round 11
// baseline (speedup 1.0000x reference)
#include <cuda_runtime.h>
#include <cuda_fp16.h>
#include <math.h>
#include <stdint.h>

// ===========================================================================
// DivFreeNetwork, forward-mode. Primal (B x 1024) and tangent (4B x 1024)
// separate; element-local fused epilogues (R9). R11: 4-stage BK=32 cp.async
// pipeline (depth 3), hi|lo packed per 128B smem row, single sync per iter.
// GEMM core: 128x64 CTA, 256 thr, warp 32x32, 2 CTAs/SM, fp16 hi/lo split
// (3 products), product-major MMA order.
// ===========================================================================

#define DM 1024
#define ODIM 448
#define NLAY 4
#define MAXB 65536
#define TROWS (4 * MAXB)

__device__ __half g_P0h[(size_t)MAXB * DM];
__device__ __half g_P0l[(size_t)MAXB * DM];
__device__ __half g_P1h[(size_t)MAXB * DM];
__device__ __half g_P1l[(size_t)MAXB * DM];
__device__ __half g_T0h[(size_t)TROWS * DM];
__device__ __half g_T0l[(size_t)TROWS * DM];
__device__ __half g_T1h[(size_t)TROWS * DM];
__device__ __half g_T1l[(size_t)TROWS * DM];
__device__ float  g_D[(size_t)MAXB * DM];
__device__ float  g_OUTP[(size_t)MAXB * ODIM];
__device__ float  g_OUTT[(size_t)TROWS * ODIM];
__device__ __half g_WThi[(size_t)NLAY * DM * DM + 512 * DM];
__device__ __half g_WTlo[(size_t)NLAY * DM * DM + 512 * DM];

__device__ __forceinline__ uint32_t smem_u32(const void* p) {
    uint32_t a;
    asm("{ .reg .u64 t; cvta.to.shared.u64 t, %1; cvt.u32.u64 %0, t; }" : "=r"(a) : "l"(p));
    return a;
}
#define SWZ(o) ((o) ^ (((o) >> 3) & 0x70))

__device__ __forceinline__ void cp16(uint32_t so, const void* g) {
    asm volatile("cp.async.cg.shared.global [%0], [%1], 16;" :: "r"(so), "l"(g));
}
__device__ __forceinline__ void ldsm4(uint32_t* r, uint32_t addr) {
    asm volatile("ldmatrix.sync.aligned.m8n8.x4.shared.b16 {%0,%1,%2,%3}, [%4];"
                 : "=r"(r[0]), "=r"(r[1]), "=r"(r[2]), "=r"(r[3]) : "r"(addr));
}
__device__ __forceinline__ void mma16816(float* c, const uint32_t* a, uint32_t b0, uint32_t b1) {
    asm volatile("mma.sync.aligned.m16n8k16.row.col.f32.f16.f16.f32 "
                 "{%0,%1,%2,%3}, {%4,%5,%6,%7}, {%8,%9}, {%0,%1,%2,%3};"
                 : "+f"(c[0]), "+f"(c[1]), "+f"(c[2]), "+f"(c[3])
                 : "r"(a[0]), "r"(a[1]), "r"(a[2]), "r"(a[3]), "r"(b0), "r"(b1));
}

__device__ __forceinline__ float sigf(float p) { return 1.0f / (1.0f + expf(-p)); }

__device__ __forceinline__ void store2split(__half* ph, __half* pl, float a, float b) {
    __half2 h;
    h.x = __float2half(a); h.y = __float2half(b);
    __half2 l;
    l.x = __float2half(a - __half2float(h.x));
    l.y = __float2half(b - __half2float(h.y));
    *(__half2*)ph = h;
    *(__half2*)pl = l;
}

__device__ __forceinline__ void store4split(__half* ph, __half* pl, float4 v) {
    __align__(8) __half h[4], l[4];
    float vv[4] = {v.x, v.y, v.z, v.w};
#pragma unroll
    for (int i = 0; i < 4; i++) {
        h[i] = __float2half(vv[i]);
        l[i] = __float2half(vv[i] - __half2float(h[i]));
    }
    *(uint2*)ph = *(uint2*)h;
    *(uint2*)pl = *(uint2*)l;
}

// ------------------ prep: transpose + hi/lo split of weights ----------------
__global__ void prep_transpose(const float* __restrict__ W,
                               __half* __restrict__ Thi,
                               __half* __restrict__ Tlo,
                               int Krows, int Ncols)
{
    __shared__ float t[32][33];
    const float* Wz = W + (size_t)blockIdx.z * Krows * Ncols;
    __half* Hz = Thi + (size_t)blockIdx.z * Ncols * Krows;
    __half* Lz = Tlo + (size_t)blockIdx.z * Ncols * Krows;
    int n0 = blockIdx.x * 32, k0 = blockIdx.y * 32;
    int tx = threadIdx.x, ty = threadIdx.y;
#pragma unroll
    for (int i = 0; i < 4; i++)
        t[ty + 8 * i][tx] = Wz[(size_t)(k0 + ty + 8 * i) * Ncols + n0 + tx];
    __syncthreads();
#pragma unroll
    for (int i = 0; i < 4; i++) {
        int n = n0 + ty + 8 * i;
        float v = t[tx][ty + 8 * i];
        __half h = __float2half(v);
        Hz[(size_t)n * Krows + k0 + tx] = h;
        Lz[(size_t)n * Krows + k0 + tx] = __float2half(v - __half2float(h));
    }
}

// ---------------- layer 0: fused input GEMV + activation -------------------
__global__ void layer0_kernel(const float* __restrict__ x,
                              const float* __restrict__ W0,
                              const float* __restrict__ b0,
                              __half* __restrict__ Ph, __half* __restrict__ Pl,
                              __half* __restrict__ Th, __half* __restrict__ Tl,
                              int B)
{
    int idx = blockIdx.x * blockDim.x + threadIdx.x;
    if (idx >= B * 256) return;
    int b = idx >> 8;
    int c = (idx & 255) * 4;
    float x0 = __ldg(x + b * 4 + 0), x1 = __ldg(x + b * 4 + 1);
    float x2 = __ldg(x + b * 4 + 2), x3 = __ldg(x + b * 4 + 3);
    float4 w0 = *(const float4*)(W0 + c);
    float4 w1 = *(const float4*)(W0 + 1024 + c);
    float4 w2 = *(const float4*)(W0 + 2048 + c);
    float4 w3 = *(const float4*)(W0 + 3072 + c);
    float4 bb = *(const float4*)(b0 + c);
    float p[4], act[4], d[4];
    float wv[4][4] = {{w0.x, w1.x, w2.x, w3.x}, {w0.y, w1.y, w2.y, w3.y},
                      {w0.z, w1.z, w2.z, w3.z}, {w0.w, w1.w, w2.w, w3.w}};
    float bv[4] = {bb.x, bb.y, bb.z, bb.w};
#pragma unroll
    for (int i = 0; i < 4; i++) {
        p[i] = fmaf(x0, wv[i][0], fmaf(x1, wv[i][1], fmaf(x2, wv[i][2], fmaf(x3, wv[i][3], bv[i]))));
        float sg = sigf(p[i]);
        act[i] = p[i] * sg;
        d[i] = sg * fmaf(p[i], 1.0f - sg, 1.0f);
    }
    size_t pb = (size_t)b * DM + c;
    store4split(Ph + pb, Pl + pb, make_float4(act[0], act[1], act[2], act[3]));
#pragma unroll
    for (int j = 0; j < 4; j++) {
        float4 t = make_float4(d[0] * wv[0][j], d[1] * wv[1][j], d[2] * wv[2][j], d[3] * wv[3][j]);
        size_t tb = ((size_t)j * B + b) * DM + c;
        store4split(Th + tb, Tl + tb, t);
    }
}

// ---------------- HMMA GEMM + element-local fused epilogue -----------------
// modes: 0 primal-hidden (bias+silu, write act + D)
//        1 tangent-hidden (scale by D, write act)
//        2 primal-out (bias, fp32 store)   3 tangent-out (fp32 store)
// Stage (BK=32 real k): A 128 rows x 128B [hi k0..31 | lo k0..31] = 16KB,
//                       B  64 rows x 128B                         =  8KB.
#define STG 24576
#define NSTAGE 4

__device__ __forceinline__ void load_stage(uint32_t sb,
    const __half* Ah, const __half* Al, const __half* Bh, const __half* Bl,
    int row0, int col0, int k0, int K, int tid)
{
    // A: 1024 cp16 slots (128 rows x 8 chunks: cc<4 hi, cc>=4 lo)
#pragma unroll
    for (int it = 0; it < 4; it++) {
        int s = tid + it * 256;
        int r = s >> 3, cc = s & 7;
        const __half* g = (cc < 4)
            ? (Ah + (size_t)(row0 + r) * K + k0 + cc * 8)
            : (Al + (size_t)(row0 + r) * K + k0 + (cc - 4) * 8);
        cp16(sb + SWZ(r * 128 + cc * 16), g);
    }
    // B: 512 cp16 slots (64 rows x 8 chunks)
#pragma unroll
    for (int it = 0; it < 2; it++) {
        int s = tid + it * 256;
        int r = s >> 3, cc = s & 7;
        const __half* g = (cc < 4)
            ? (Bh + (size_t)(col0 + r) * K + k0 + cc * 8)
            : (Bl + (size_t)(col0 + r) * K + k0 + (cc - 4) * 8);
        cp16(sb + 16384u + SWZ(r * 128 + cc * 16), g);
    }
    asm volatile("cp.async.commit_group;" ::: "memory");
}

__global__ void __launch_bounds__(256, 2)
gemm_fused(const __half* __restrict__ Ain, const __half* __restrict__ Alin,
           const __half* __restrict__ Bh, const __half* __restrict__ Bl,
           const float* __restrict__ bias,
           __half* __restrict__ Oh, __half* __restrict__ Ol,
           float* __restrict__ Dbuf, float* __restrict__ C,
           int K, int ldc, int Nstore, int Bn, int mode)
{
    extern __shared__ char smem[];
    uint32_t sbase = smem_u32(smem);
    int tid = threadIdx.x, wid = tid >> 5, lid = tid & 31;
    int wm = wid & 3, wn = wid >> 2;
    int row0 = blockIdx.y * 128;
    int col0 = blockIdx.x * 64;

    float acc[2][4][4];
#pragma unroll
    for (int i = 0; i < 2; i++)
#pragma unroll
        for (int j = 0; j < 4; j++)
#pragma unroll
            for (int q = 0; q < 4; q++) acc[i][j][q] = 0.0f;

    const int KITER = K >> 5;   // BK = 32
    load_stage(sbase + 0 * STG, Ain, Alin, Bh, Bl, row0, col0, 0, K, tid);
    load_stage(sbase + 1 * STG, Ain, Alin, Bh, Bl, row0, col0, 32, K, tid);
    load_stage(sbase + 2 * STG, Ain, Alin, Bh, Bl, row0, col0, 64, K, tid);

    int lrow = lid & 15;
    int kadd2 = (lid & 16) ? 16 : 0;     // byte offset of upper k-half

    // hoisted swizzle: SWZ(row*128 + c2) = row*128 + (c2 ^ mask), c2 < 128
    uint32_t arow[2], amask[2], brow[2], bmask[2];
#pragma unroll
    for (int mi = 0; mi < 2; mi++) {
        uint32_t r = (wm * 32 + mi * 16 + lrow) * 128u;
        arow[mi] = r;
        amask[mi] = (r >> 3) & 0x70u;
    }
#pragma unroll
    for (int j = 0; j < 2; j++) {
        uint32_t r = (wn * 32 + j * 16 + lrow) * 128u;
        brow[j] = r;
        bmask[j] = (r >> 3) & 0x70u;
    }

    for (int i = 0; i < KITER; i++) {
        asm volatile("cp.async.wait_group 2;" ::: "memory");
        __syncthreads();
        uint32_t stg = sbase + (i & 3) * STG;

        // issue next stage immediately (buffer (i+3)%4 was consumed at i-1)
        if (i + 3 < KITER)
            load_stage(sbase + ((i + 3) & 3) * STG, Ain, Alin, Bh, Bl,
                       row0, col0, (i + 3) * 32, K, tid);
        else
            asm volatile("cp.async.commit_group;" ::: "memory");

#pragma unroll
        for (int ks = 0; ks < 2; ks++) {
            uint32_t c2 = ks * 32 + kadd2;           // hi plane: bytes [0,64)
            uint32_t c2l = c2 + 64;                  // lo plane: bytes [64,128)
            uint32_t ahi[2][4], alo[2][4], bhi[2][4], blo[2][4];
#pragma unroll
            for (int mi = 0; mi < 2; mi++)
                ldsm4(ahi[mi], stg + arow[mi] + (c2 ^ amask[mi]));
#pragma unroll
            for (int j = 0; j < 2; j++)
                ldsm4(bhi[j], stg + 16384u + brow[j] + (c2 ^ bmask[j]));
#pragma unroll
            for (int j = 0; j < 2; j++)
                ldsm4(blo[j], stg + 16384u + brow[j] + (c2l ^ bmask[j]));
            // product 1: hi*hi
#pragma unroll
            for (int mi = 0; mi < 2; mi++)
#pragma unroll
                for (int j = 0; j < 2; j++) {
                    mma16816(acc[mi][2 * j],     ahi[mi], bhi[j][0], bhi[j][2]);
                    mma16816(acc[mi][2 * j + 1], ahi[mi], bhi[j][1], bhi[j][3]);
                }
#pragma unroll
            for (int mi = 0; mi < 2; mi++)
                ldsm4(alo[mi], stg + arow[mi] + (c2l ^ amask[mi]));
            // product 2: hi*lo
#pragma unroll
            for (int mi = 0; mi < 2; mi++)
#pragma unroll
                for (int j = 0; j < 2; j++) {
                    mma16816(acc[mi][2 * j],     ahi[mi], blo[j][0], blo[j][2]);
                    mma16816(acc[mi][2 * j + 1], ahi[mi], blo[j][1], blo[j][3]);
                }
            // product 3: lo*hi
#pragma unroll
            for (int mi = 0; mi < 2; mi++)
#pragma unroll
                for (int j = 0; j < 2; j++) {
                    mma16816(acc[mi][2 * j],     alo[mi], bhi[j][0], bhi[j][2]);
                    mma16816(acc[mi][2 * j + 1], alo[mi], bhi[j][1], bhi[j][3]);
                }
        }
    }

    int trow = lid >> 2, tcol = (lid & 3) * 2;
    int jB = (mode == 1 || mode == 3) ? (row0 / Bn) * Bn : 0;

#pragma unroll
    for (int mi = 0; mi < 2; mi++) {
#pragma unroll
        for (int j = 0; j < 4; j++) {
            int gc = col0 + wn * 32 + j * 8 + tcol;
#pragma unroll
            for (int hv = 0; hv < 2; hv++) {
                int gr = row0 + wm * 32 + mi * 16 + trow + hv * 8;
                float a0 = acc[mi][j][2 * hv], a1 = acc[mi][j][2 * hv + 1];
                if (mode == 0) {
                    float p0 = a0 + bias[gc], p1 = a1 + bias[gc + 1];
                    float s0 = sigf(p0), s1 = sigf(p1);
                    size_t o = (size_t)gr * DM + gc;
                    store2split(Oh + o, Ol + o, p0 * s0, p1 * s1);
                    float2 dd;
                    dd.x = s0 * fmaf(p0, 1.0f - s0, 1.0f);
                    dd.y = s1 * fmaf(p1, 1.0f - s1, 1.0f);
                    *(float2*)(Dbuf + o) = dd;
                } else if (mode == 1) {
                    float2 dd = *(const float2*)(Dbuf + (size_t)(gr - jB) * DM + gc);
                    size_t o = (size_t)gr * DM + gc;
                    store2split(Oh + o, Ol + o, a0 * dd.x, a1 * dd.y);
                } else {
                    if (gc < Nstore) {
                        float2 v = make_float2(a0, a1);
                        if (mode == 2) { v.x += bias[gc]; v.y += bias[gc + 1]; }
                        *(float2*)(C + (size_t)gr * ldc + gc) = v;
                    }
                }
            }
        }
    }
}

// ---------------- head: softmax-mixture derivative, warp per point ---------
__global__ void finalize_kernel(const float* __restrict__ OUTP,
                                const float* __restrict__ OUTT,
                                float* __restrict__ y, int B)
{
    int warp = (blockIdx.x * blockDim.x + threadIdx.x) >> 5;
    int lane = threadIdx.x & 31;
    if (warp >= B) return;
    const float* o = OUTP + (size_t)warp * ODIM;

    float l0 = o[lane], l1 = o[lane + 32];
    float m = fmaxf(l0, l1);
#pragma unroll
    for (int s = 16; s; s >>= 1) m = fmaxf(m, __shfl_xor_sync(0xFFFFFFFFu, m, s));
    float e0 = expf(l0 - m), e1 = expf(l1 - m);
    float S = e0 + e1;
#pragma unroll
    for (int s = 16; s; s >>= 1) S += __shfl_xor_sync(0xFFFFFFFFu, S, s);
    float s0 = e0 / S, s1 = e1 / S;

    float v0[6], v1[6];
#pragma unroll
    for (int t = 0; t < 6; t++) {
        v0[t] = o[64 + 6 * lane + t];
        v1[t] = o[64 + 6 * (lane + 32) + t];
    }

    float Dm[4][6];
#pragma unroll
    for (int j = 0; j < 4; j++) {
        const float* tj = OUTT + ((size_t)j * B + warp) * ODIM;
        float g0 = tj[lane], g1 = tj[lane + 32];
        float dot = s0 * g0 + s1 * g1;
#pragma unroll
        for (int s = 16; s; s >>= 1) dot += __shfl_xor_sync(0xFFFFFFFFu, dot, s);
#pragma unroll
        for (int t = 0; t < 6; t++) {
            float dv0 = tj[64 + 6 * lane + t];
            float dv1 = tj[64 + 6 * (lane + 32) + t];
            float val = s0 * fmaf(g0 - dot, v0[t], dv0) + s1 * fmaf(g1 - dot, v1[t], dv1);
#pragma unroll
            for (int s = 16; s; s >>= 1) val += __shfl_xor_sync(0xFFFFFFFFu, val, s);
            Dm[j][t] = val;
        }
    }
    if (lane == 0) {
        float u0 =  Dm[1][0] + Dm[2][1] + Dm[3][2];
        float u1 = -Dm[0][0] + Dm[2][3] + Dm[3][4];
        float u2 = -Dm[0][1] - Dm[1][3] + Dm[3][5];
        float u3 = -Dm[0][2] - Dm[1][4] - Dm[2][5];
        *(float4*)(y + (size_t)warp * 4) = make_float4(u0 * 10.0f, u1, u2, u3);
    }
}

// ---------------------------------------------------------------------------
extern "C" void kernel_launch(void* const* d_in, const int* in_sizes, int n_in,
                              void* d_out, int out_size)
{
    const float* x    = (const float*)d_in[0];
    const float* W0   = (const float*)d_in[1];
    const float* b0   = (const float*)d_in[2];
    const float* Wh   = (const float*)d_in[3];
    const float* bh   = (const float*)d_in[4];
    const float* Wout = (const float*)d_in[5];
    const float* bout = (const float*)d_in[6];
    float* y = (float*)d_out;

    int B = in_sizes[0] / 4;

    __half *P0h, *P0l, *P1h, *P1l, *T0h, *T0l, *T1h, *T1l, *WThi, *WTlo;
    float *Dbuf, *OUTP, *OUTT;
    cudaGetSymbolAddress((void**)&P0h, g_P0h);
    cudaGetSymbolAddress((void**)&P0l, g_P0l);
    cudaGetSymbolAddress((void**)&P1h, g_P1h);
    cudaGetSymbolAddress((void**)&P1l, g_P1l);
    cudaGetSymbolAddress((void**)&T0h, g_T0h);
    cudaGetSymbolAddress((void**)&T0l, g_T0l);
    cudaGetSymbolAddress((void**)&T1h, g_T1h);
    cudaGetSymbolAddress((void**)&T1l, g_T1l);
    cudaGetSymbolAddress((void**)&Dbuf, g_D);
    cudaGetSymbolAddress((void**)&OUTP, g_OUTP);
    cudaGetSymbolAddress((void**)&OUTT, g_OUTT);
    cudaGetSymbolAddress((void**)&WThi, g_WThi);
    cudaGetSymbolAddress((void**)&WTlo, g_WTlo);

    static int smem_set = 0;
    if (!smem_set) {
        cudaFuncSetAttribute(gemm_fused, cudaFuncAttributeMaxDynamicSharedMemorySize,
                             NSTAGE * STG);
        smem_set = 1;
    }

    prep_transpose<<<dim3(32, 32, NLAY), dim3(32, 8)>>>(Wh, WThi, WTlo, DM, DM);
    prep_transpose<<<dim3(ODIM / 32, 32, 1), dim3(32, 8)>>>(
        Wout, WThi + (size_t)NLAY * DM * DM, WTlo + (size_t)NLAY * DM * DM, DM, ODIM);

    layer0_kernel<<<(B * 256 + 255) / 256, 256>>>(x, W0, b0, P0h, P0l, T0h, T0l, B);

    __half *pch = P0h, *pcl = P0l, *pnh = P1h, *pnl = P1l;
    __half *tch = T0h, *tcl = T0l, *tnh = T1h, *tnl = T1l;

    dim3 gP(DM / 64, B / 128);
    dim3 gT(DM / 64, (4 * B) / 128);
    for (int l = 0; l < NLAY; l++) {
        const __half* wh = WThi + (size_t)l * DM * DM;
        const __half* wl = WTlo + (size_t)l * DM * DM;
        gemm_fused<<<gP, 256, NSTAGE * STG>>>(pch, pcl, wh, wl,
            bh + (size_t)l * DM, pnh, pnl, Dbuf, nullptr, DM, 0, 0, B, 0);
        gemm_fused<<<gT, 256, NSTAGE * STG>>>(tch, tcl, wh, wl,
            nullptr, tnh, tnl, Dbuf, nullptr, DM, 0, 0, B, 1);
        __half* t;
        t = pch; pch = pnh; pnh = t;  t = pcl; pcl = pnl; pnl = t;
        t = tch; tch = tnh; tnh = t;  t = tcl; tcl = tnl; tnl = t;
    }

    const __half* woh = WThi + (size_t)NLAY * DM * DM;
    const __half* wol = WTlo + (size_t)NLAY * DM * DM;
    dim3 gPo(ODIM / 64, B / 128);          // 7 column tiles: N=448 exactly
    dim3 gTo(ODIM / 64, (4 * B) / 128);
    gemm_fused<<<gPo, 256, NSTAGE * STG>>>(pch, pcl, woh, wol,
        bout, nullptr, nullptr, nullptr, OUTP, DM, ODIM, ODIM, B, 2);
    gemm_fused<<<gTo, 256, NSTAGE * STG>>>(tch, tcl, woh, wol,
        nullptr, nullptr, nullptr, nullptr, OUTT, DM, ODIM, ODIM, B, 3);

    finalize_kernel<<<(B * 32 + 255) / 256, 256>>>(OUTP, OUTT, y, B);
}

// round 12
// speedup vs baseline: 1.0192x; 1.0192x over previous
#include <cuda_runtime.h>
#include <cuda_fp16.h>
#include <math.h>
#include <stdint.h>

// ===========================================================================
// DivFreeNetwork, forward-mode. Primal (B x 1024) and tangent (4B x 1024)
// separate; element-local fused epilogues (R9).
// R12: CTA 128x128, warp 32x64 (MMA:LDSM = 4.0), BK=32 hi|lo-packed rows,
//      3-stage cp.async, 2 CTAs/SM, b-fragments in two j-halves to cap regs.
// ===========================================================================

#define DM 1024
#define ODIM 448
#define NLAY 4
#define MAXB 65536
#define TROWS (4 * MAXB)

__device__ __half g_P0h[(size_t)MAXB * DM];
__device__ __half g_P0l[(size_t)MAXB * DM];
__device__ __half g_P1h[(size_t)MAXB * DM];
__device__ __half g_P1l[(size_t)MAXB * DM];
__device__ __half g_T0h[(size_t)TROWS * DM];
__device__ __half g_T0l[(size_t)TROWS * DM];
__device__ __half g_T1h[(size_t)TROWS * DM];
__device__ __half g_T1l[(size_t)TROWS * DM];
__device__ float  g_D[(size_t)MAXB * DM];
__device__ float  g_OUTP[(size_t)MAXB * ODIM];
__device__ float  g_OUTT[(size_t)TROWS * ODIM];
__device__ __half g_WThi[(size_t)NLAY * DM * DM + 512 * DM];
__device__ __half g_WTlo[(size_t)NLAY * DM * DM + 512 * DM];

__device__ __forceinline__ uint32_t smem_u32(const void* p) {
    uint32_t a;
    asm("{ .reg .u64 t; cvta.to.shared.u64 t, %1; cvt.u32.u64 %0, t; }" : "=r"(a) : "l"(p));
    return a;
}
#define SWZ(o) ((o) ^ (((o) >> 3) & 0x70))

__device__ __forceinline__ void cp16(uint32_t so, const void* g) {
    asm volatile("cp.async.cg.shared.global [%0], [%1], 16;" :: "r"(so), "l"(g));
}
__device__ __forceinline__ void ldsm4(uint32_t* r, uint32_t addr) {
    asm volatile("ldmatrix.sync.aligned.m8n8.x4.shared.b16 {%0,%1,%2,%3}, [%4];"
                 : "=r"(r[0]), "=r"(r[1]), "=r"(r[2]), "=r"(r[3]) : "r"(addr));
}
__device__ __forceinline__ void mma16816(float* c, const uint32_t* a, uint32_t b0, uint32_t b1) {
    asm volatile("mma.sync.aligned.m16n8k16.row.col.f32.f16.f16.f32 "
                 "{%0,%1,%2,%3}, {%4,%5,%6,%7}, {%8,%9}, {%0,%1,%2,%3};"
                 : "+f"(c[0]), "+f"(c[1]), "+f"(c[2]), "+f"(c[3])
                 : "r"(a[0]), "r"(a[1]), "r"(a[2]), "r"(a[3]), "r"(b0), "r"(b1));
}

__device__ __forceinline__ float sigf(float p) { return 1.0f / (1.0f + expf(-p)); }

__device__ __forceinline__ void store2split(__half* ph, __half* pl, float a, float b) {
    __half2 h;
    h.x = __float2half(a); h.y = __float2half(b);
    __half2 l;
    l.x = __float2half(a - __half2float(h.x));
    l.y = __float2half(b - __half2float(h.y));
    *(__half2*)ph = h;
    *(__half2*)pl = l;
}

__device__ __forceinline__ void store4split(__half* ph, __half* pl, float4 v) {
    __align__(8) __half h[4], l[4];
    float vv[4] = {v.x, v.y, v.z, v.w};
#pragma unroll
    for (int i = 0; i < 4; i++) {
        h[i] = __float2half(vv[i]);
        l[i] = __float2half(vv[i] - __half2float(h[i]));
    }
    *(uint2*)ph = *(uint2*)h;
    *(uint2*)pl = *(uint2*)l;
}

// ------------------ prep: transpose + hi/lo split of weights ----------------
__global__ void prep_transpose(const float* __restrict__ W,
                               __half* __restrict__ Thi,
                               __half* __restrict__ Tlo,
                               int Krows, int Ncols)
{
    __shared__ float t[32][33];
    const float* Wz = W + (size_t)blockIdx.z * Krows * Ncols;
    __half* Hz = Thi + (size_t)blockIdx.z * Ncols * Krows;
    __half* Lz = Tlo + (size_t)blockIdx.z * Ncols * Krows;
    int n0 = blockIdx.x * 32, k0 = blockIdx.y * 32;
    int tx = threadIdx.x, ty = threadIdx.y;
#pragma unroll
    for (int i = 0; i < 4; i++)
        t[ty + 8 * i][tx] = Wz[(size_t)(k0 + ty + 8 * i) * Ncols + n0 + tx];
    __syncthreads();
#pragma unroll
    for (int i = 0; i < 4; i++) {
        int n = n0 + ty + 8 * i;
        float v = t[tx][ty + 8 * i];
        __half h = __float2half(v);
        Hz[(size_t)n * Krows + k0 + tx] = h;
        Lz[(size_t)n * Krows + k0 + tx] = __float2half(v - __half2float(h));
    }
}

// ---------------- layer 0: fused input GEMV + activation -------------------
__global__ void layer0_kernel(const float* __restrict__ x,
                              const float* __restrict__ W0,
                              const float* __restrict__ b0,
                              __half* __restrict__ Ph, __half* __restrict__ Pl,
                              __half* __restrict__ Th, __half* __restrict__ Tl,
                              int B)
{
    int idx = blockIdx.x * blockDim.x + threadIdx.x;
    if (idx >= B * 256) return;
    int b = idx >> 8;
    int c = (idx & 255) * 4;
    float x0 = __ldg(x + b * 4 + 0), x1 = __ldg(x + b * 4 + 1);
    float x2 = __ldg(x + b * 4 + 2), x3 = __ldg(x + b * 4 + 3);
    float4 w0 = *(const float4*)(W0 + c);
    float4 w1 = *(const float4*)(W0 + 1024 + c);
    float4 w2 = *(const float4*)(W0 + 2048 + c);
    float4 w3 = *(const float4*)(W0 + 3072 + c);
    float4 bb = *(const float4*)(b0 + c);
    float p[4], act[4], d[4];
    float wv[4][4] = {{w0.x, w1.x, w2.x, w3.x}, {w0.y, w1.y, w2.y, w3.y},
                      {w0.z, w1.z, w2.z, w3.z}, {w0.w, w1.w, w2.w, w3.w}};
    float bv[4] = {bb.x, bb.y, bb.z, bb.w};
#pragma unroll
    for (int i = 0; i < 4; i++) {
        p[i] = fmaf(x0, wv[i][0], fmaf(x1, wv[i][1], fmaf(x2, wv[i][2], fmaf(x3, wv[i][3], bv[i]))));
        float sg = sigf(p[i]);
        act[i] = p[i] * sg;
        d[i] = sg * fmaf(p[i], 1.0f - sg, 1.0f);
    }
    size_t pb = (size_t)b * DM + c;
    store4split(Ph + pb, Pl + pb, make_float4(act[0], act[1], act[2], act[3]));
#pragma unroll
    for (int j = 0; j < 4; j++) {
        float4 t = make_float4(d[0] * wv[0][j], d[1] * wv[1][j], d[2] * wv[2][j], d[3] * wv[3][j]);
        size_t tb = ((size_t)j * B + b) * DM + c;
        store4split(Th + tb, Tl + tb, t);
    }
}

// ---------------- HMMA GEMM + element-local fused epilogue -----------------
// modes: 0 primal-hidden (bias+silu, write act + D)
//        1 tangent-hidden (scale by D, write act)
//        2 primal-out (bias, fp32 store)   3 tangent-out (fp32 store)
// Stage (BK=32): A 128 rows x 128B [hi k0..31 | lo k0..31] = 16KB,
//                B 128 rows x 128B                         = 16KB.
#define STG 32768
#define NSTAGE 3

__device__ __forceinline__ void load_stage(uint32_t sb,
    const __half* Ah, const __half* Al, const __half* Bh, const __half* Bl,
    int row0, int col0, int k0, int K, int tid)
{
    // A: 1024 cp16 slots (128 rows x 8 chunks: cc<4 hi, cc>=4 lo)
#pragma unroll
    for (int it = 0; it < 4; it++) {
        int s = tid + it * 256;
        int r = s >> 3, cc = s & 7;
        const __half* g = (cc < 4)
            ? (Ah + (size_t)(row0 + r) * K + k0 + cc * 8)
            : (Al + (size_t)(row0 + r) * K + k0 + (cc - 4) * 8);
        cp16(sb + SWZ(r * 128 + cc * 16), g);
    }
    // B: 1024 cp16 slots (128 rows x 8 chunks)
#pragma unroll
    for (int it = 0; it < 4; it++) {
        int s = tid + it * 256;
        int r = s >> 3, cc = s & 7;
        const __half* g = (cc < 4)
            ? (Bh + (size_t)(col0 + r) * K + k0 + cc * 8)
            : (Bl + (size_t)(col0 + r) * K + k0 + (cc - 4) * 8);
        cp16(sb + 16384u + SWZ(r * 128 + cc * 16), g);
    }
    asm volatile("cp.async.commit_group;" ::: "memory");
}

__global__ void __launch_bounds__(256, 2)
gemm_fused(const __half* __restrict__ Ain, const __half* __restrict__ Alin,
           const __half* __restrict__ Bh, const __half* __restrict__ Bl,
           const float* __restrict__ bias,
           __half* __restrict__ Oh, __half* __restrict__ Ol,
           float* __restrict__ Dbuf, float* __restrict__ C,
           int K, int ldc, int Nstore, int Bn, int mode)
{
    extern __shared__ char smem[];
    uint32_t sbase = smem_u32(smem);
    int tid = threadIdx.x, wid = tid >> 5, lid = tid & 31;
    int wm = wid & 3, wn = wid >> 2;     // 4 warps M (32 rows), 2 warps N (64 cols)
    int row0 = blockIdx.y * 128;
    int col0 = blockIdx.x * 128;

    float acc[2][8][4];
#pragma unroll
    for (int i = 0; i < 2; i++)
#pragma unroll
        for (int j = 0; j < 8; j++)
#pragma unroll
            for (int q = 0; q < 4; q++) acc[i][j][q] = 0.0f;

    const int KITER = K >> 5;   // BK = 32
    load_stage(sbase + 0 * STG, Ain, Alin, Bh, Bl, row0, col0, 0, K, tid);
    load_stage(sbase + 1 * STG, Ain, Alin, Bh, Bl, row0, col0, 32, K, tid);

    int lrow = lid & 15;
    int kadd2 = (lid & 16) ? 16 : 0;     // byte offset of upper k-half

    // hoisted swizzle: SWZ(row*128 + c2) = row*128 + (c2 ^ mask), c2 < 128
    uint32_t arow[2], amask[2], brow[4], bmask[4];
#pragma unroll
    for (int mi = 0; mi < 2; mi++) {
        uint32_t r = (wm * 32 + mi * 16 + lrow) * 128u;
        arow[mi] = r;
        amask[mi] = (r >> 3) & 0x70u;
    }
#pragma unroll
    for (int j = 0; j < 4; j++) {
        uint32_t r = (wn * 64 + j * 16 + lrow) * 128u;
        brow[j] = r;
        bmask[j] = (r >> 3) & 0x70u;
    }

    int sc = 0, sl = 2;                  // compute / load stage indices (mod 3)
    for (int i = 0; i < KITER; i++) {
        asm volatile("cp.async.wait_group 1;" ::: "memory");
        __syncthreads();
        uint32_t stg = sbase + sc * STG;

        if (i + 2 < KITER)
            load_stage(sbase + sl * STG, Ain, Alin, Bh, Bl,
                       row0, col0, (i + 2) * 32, K, tid);
        else
            asm volatile("cp.async.commit_group;" ::: "memory");

#pragma unroll
        for (int ks = 0; ks < 2; ks++) {
            uint32_t c2 = ks * 32 + kadd2;          // hi plane bytes [0,64)
            uint32_t c2l = c2 + 64;                 // lo plane bytes [64,128)
            uint32_t ahi[2][4], alo[2][4];
#pragma unroll
            for (int mi = 0; mi < 2; mi++) {
                ldsm4(ahi[mi], stg + arow[mi] + (c2 ^ amask[mi]));
                ldsm4(alo[mi], stg + arow[mi] + (c2l ^ amask[mi]));
            }
            // two j-halves to cap live fragment registers
#pragma unroll
            for (int jj = 0; jj < 2; jj++) {
                uint32_t bhi[2][4], blo[2][4];
#pragma unroll
                for (int j = 0; j < 2; j++) {
                    int jb = jj * 2 + j;
                    ldsm4(bhi[j], stg + 16384u + brow[jb] + (c2 ^ bmask[jb]));
                    ldsm4(blo[j], stg + 16384u + brow[jb] + (c2l ^ bmask[jb]));
                }
                // product 1: hi*hi
#pragma unroll
                for (int mi = 0; mi < 2; mi++)
#pragma unroll
                    for (int j = 0; j < 2; j++) {
                        int ja = jj * 4 + 2 * j;
                        mma16816(acc[mi][ja],     ahi[mi], bhi[j][0], bhi[j][2]);
                        mma16816(acc[mi][ja + 1], ahi[mi], bhi[j][1], bhi[j][3]);
                    }
                // product 2: hi*lo
#pragma unroll
                for (int mi = 0; mi < 2; mi++)
#pragma unroll
                    for (int j = 0; j < 2; j++) {
                        int ja = jj * 4 + 2 * j;
                        mma16816(acc[mi][ja],     ahi[mi], blo[j][0], blo[j][2]);
                        mma16816(acc[mi][ja + 1], ahi[mi], blo[j][1], blo[j][3]);
                    }
                // product 3: lo*hi
#pragma unroll
                for (int mi = 0; mi < 2; mi++)
#pragma unroll
                    for (int j = 0; j < 2; j++) {
                        int ja = jj * 4 + 2 * j;
                        mma16816(acc[mi][ja],     alo[mi], bhi[j][0], bhi[j][2]);
                        mma16816(acc[mi][ja + 1], alo[mi], bhi[j][1], bhi[j][3]);
                    }
            }
        }
        sc = (sc == 2) ? 0 : sc + 1;
        sl = (sl == 2) ? 0 : sl + 1;
    }

    int trow = lid >> 2, tcol = (lid & 3) * 2;
    int jB = (mode == 1 || mode == 3) ? (row0 / Bn) * Bn : 0;

#pragma unroll
    for (int mi = 0; mi < 2; mi++) {
#pragma unroll
        for (int j = 0; j < 8; j++) {
            int gc = col0 + wn * 64 + j * 8 + tcol;
#pragma unroll
            for (int hv = 0; hv < 2; hv++) {
                int gr = row0 + wm * 32 + mi * 16 + trow + hv * 8;
                float a0 = acc[mi][j][2 * hv], a1 = acc[mi][j][2 * hv + 1];
                if (mode == 0) {
                    float p0 = a0 + bias[gc], p1 = a1 + bias[gc + 1];
                    float s0 = sigf(p0), s1 = sigf(p1);
                    size_t o = (size_t)gr * DM + gc;
                    store2split(Oh + o, Ol + o, p0 * s0, p1 * s1);
                    float2 dd;
                    dd.x = s0 * fmaf(p0, 1.0f - s0, 1.0f);
                    dd.y = s1 * fmaf(p1, 1.0f - s1, 1.0f);
                    *(float2*)(Dbuf + o) = dd;
                } else if (mode == 1) {
                    float2 dd = *(const float2*)(Dbuf + (size_t)(gr - jB) * DM + gc);
                    size_t o = (size_t)gr * DM + gc;
                    store2split(Oh + o, Ol + o, a0 * dd.x, a1 * dd.y);
                } else {
                    if (gc < Nstore) {
                        float2 v = make_float2(a0, a1);
                        if (mode == 2) { v.x += bias[gc]; v.y += bias[gc + 1]; }
                        *(float2*)(C + (size_t)gr * ldc + gc) = v;
                    }
                }
            }
        }
    }
}

// ---------------- head: softmax-mixture derivative, warp per point ---------
__global__ void finalize_kernel(const float* __restrict__ OUTP,
                                const float* __restrict__ OUTT,
                                float* __restrict__ y, int B)
{
    int warp = (blockIdx.x * blockDim.x + threadIdx.x) >> 5;
    int lane = threadIdx.x & 31;
    if (warp >= B) return;
    const float* o = OUTP + (size_t)warp * ODIM;

    float l0 = o[lane], l1 = o[lane + 32];
    float m = fmaxf(l0, l1);
#pragma unroll
    for (int s = 16; s; s >>= 1) m = fmaxf(m, __shfl_xor_sync(0xFFFFFFFFu, m, s));
    float e0 = expf(l0 - m), e1 = expf(l1 - m);
    float S = e0 + e1;
#pragma unroll
    for (int s = 16; s; s >>= 1) S += __shfl_xor_sync(0xFFFFFFFFu, S, s);
    float s0 = e0 / S, s1 = e1 / S;

    float v0[6], v1[6];
#pragma unroll
    for (int t = 0; t < 6; t++) {
        v0[t] = o[64 + 6 * lane + t];
        v1[t] = o[64 + 6 * (lane + 32) + t];
    }

    float Dm[4][6];
#pragma unroll
    for (int j = 0; j < 4; j++) {
        const float* tj = OUTT + ((size_t)j * B + warp) * ODIM;
        float g0 = tj[lane], g1 = tj[lane + 32];
        float dot = s0 * g0 + s1 * g1;
#pragma unroll
        for (int s = 16; s; s >>= 1) dot += __shfl_xor_sync(0xFFFFFFFFu, dot, s);
#pragma unroll
        for (int t = 0; t < 6; t++) {
            float dv0 = tj[64 + 6 * lane + t];
            float dv1 = tj[64 + 6 * (lane + 32) + t];
            float val = s0 * fmaf(g0 - dot, v0[t], dv0) + s1 * fmaf(g1 - dot, v1[t], dv1);
#pragma unroll
            for (int s = 16; s; s >>= 1) val += __shfl_xor_sync(0xFFFFFFFFu, val, s);
            Dm[j][t] = val;
        }
    }
    if (lane == 0) {
        float u0 =  Dm[1][0] + Dm[2][1] + Dm[3][2];
        float u1 = -Dm[0][0] + Dm[2][3] + Dm[3][4];
        float u2 = -Dm[0][1] - Dm[1][3] + Dm[3][5];
        float u3 = -Dm[0][2] - Dm[1][4] - Dm[2][5];
        *(float4*)(y + (size_t)warp * 4) = make_float4(u0 * 10.0f, u1, u2, u3);
    }
}

// ---------------------------------------------------------------------------
extern "C" void kernel_launch(void* const* d_in, const int* in_sizes, int n_in,
                              void* d_out, int out_size)
{
    const float* x    = (const float*)d_in[0];
    const float* W0   = (const float*)d_in[1];
    const float* b0   = (const float*)d_in[2];
    const float* Wh   = (const float*)d_in[3];
    const float* bh   = (const float*)d_in[4];
    const float* Wout = (const float*)d_in[5];
    const float* bout = (const float*)d_in[6];
    float* y = (float*)d_out;

    int B = in_sizes[0] / 4;

    __half *P0h, *P0l, *P1h, *P1l, *T0h, *T0l, *T1h, *T1l, *WThi, *WTlo;
    float *Dbuf, *OUTP, *OUTT;
    cudaGetSymbolAddress((void**)&P0h, g_P0h);
    cudaGetSymbolAddress((void**)&P0l, g_P0l);
    cudaGetSymbolAddress((void**)&P1h, g_P1h);
    cudaGetSymbolAddress((void**)&P1l, g_P1l);
    cudaGetSymbolAddress((void**)&T0h, g_T0h);
    cudaGetSymbolAddress((void**)&T0l, g_T0l);
    cudaGetSymbolAddress((void**)&T1h, g_T1h);
    cudaGetSymbolAddress((void**)&T1l, g_T1l);
    cudaGetSymbolAddress((void**)&Dbuf, g_D);
    cudaGetSymbolAddress((void**)&OUTP, g_OUTP);
    cudaGetSymbolAddress((void**)&OUTT, g_OUTT);
    cudaGetSymbolAddress((void**)&WThi, g_WThi);
    cudaGetSymbolAddress((void**)&WTlo, g_WTlo);

    static int smem_set = 0;
    if (!smem_set) {
        cudaFuncSetAttribute(gemm_fused, cudaFuncAttributeMaxDynamicSharedMemorySize,
                             NSTAGE * STG);
        smem_set = 1;
    }

    prep_transpose<<<dim3(32, 32, NLAY), dim3(32, 8)>>>(Wh, WThi, WTlo, DM, DM);
    prep_transpose<<<dim3(ODIM / 32, 32, 1), dim3(32, 8)>>>(
        Wout, WThi + (size_t)NLAY * DM * DM, WTlo + (size_t)NLAY * DM * DM, DM, ODIM);

    layer0_kernel<<<(B * 256 + 255) / 256, 256>>>(x, W0, b0, P0h, P0l, T0h, T0l, B);

    __half *pch = P0h, *pcl = P0l, *pnh = P1h, *pnl = P1l;
    __half *tch = T0h, *tcl = T0l, *tnh = T1h, *tnl = T1l;

    dim3 gP(DM / 128, B / 128);
    dim3 gT(DM / 128, (4 * B) / 128);
    for (int l = 0; l < NLAY; l++) {
        const __half* wh = WThi + (size_t)l * DM * DM;
        const __half* wl = WTlo + (size_t)l * DM * DM;
        gemm_fused<<<gP, 256, NSTAGE * STG>>>(pch, pcl, wh, wl,
            bh + (size_t)l * DM, pnh, pnl, Dbuf, nullptr, DM, 0, 0, B, 0);
        gemm_fused<<<gT, 256, NSTAGE * STG>>>(tch, tcl, wh, wl,
            nullptr, tnh, tnl, Dbuf, nullptr, DM, 0, 0, B, 1);
        __half* t;
        t = pch; pch = pnh; pnh = t;  t = pcl; pcl = pnl; pnl = t;
        t = tch; tch = tnh; tnh = t;  t = tcl; tcl = tnl; tnl = t;
    }

    const __half* woh = WThi + (size_t)NLAY * DM * DM;
    const __half* wol = WTlo + (size_t)NLAY * DM * DM;
    dim3 gPo(4, B / 128);                // 4 x 128 cols (weights padded to 512)
    dim3 gTo(4, (4 * B) / 128);
    gemm_fused<<<gPo, 256, NSTAGE * STG>>>(pch, pcl, woh, wol,
        bout, nullptr, nullptr, nullptr, OUTP, DM, ODIM, ODIM, B, 2);
    gemm_fused<<<gTo, 256, NSTAGE * STG>>>(tch, tcl, woh, wol,
        nullptr, nullptr, nullptr, nullptr, OUTT, DM, ODIM, ODIM, B, 3);

    finalize_kernel<<<(B * 32 + 255) / 256, 256>>>(OUTP, OUTT, y, B);
}

// round 13
// speedup vs baseline: 1.1335x; 1.1121x over previous
#include <cuda_runtime.h>
#include <cuda_fp16.h>
#include <math.h>
#include <stdint.h>

// ===========================================================================
// DivFreeNetwork, forward-mode. Primal (B x 1024) and tangent (4B x 1024)
// separate; element-local fused epilogues. R13 = R9 GEMM core verbatim
// (empirical optimum: BK=64, 4 flat planes, 2-stage, 128x64, 2 CTAs/SM)
// + 7-tile output GEMMs + dual-stream P/T overlap (D double-buffered).
// ===========================================================================

#define DM 1024
#define ODIM 448
#define NLAY 4
#define MAXB 65536
#define TROWS (4 * MAXB)

__device__ __half g_P0h[(size_t)MAXB * DM];
__device__ __half g_P0l[(size_t)MAXB * DM];
__device__ __half g_P1h[(size_t)MAXB * DM];
__device__ __half g_P1l[(size_t)MAXB * DM];
__device__ __half g_T0h[(size_t)TROWS * DM];
__device__ __half g_T0l[(size_t)TROWS * DM];
__device__ __half g_T1h[(size_t)TROWS * DM];
__device__ __half g_T1l[(size_t)TROWS * DM];
__device__ float  g_D0[(size_t)MAXB * DM];
__device__ float  g_D1[(size_t)MAXB * DM];
__device__ float  g_OUTP[(size_t)MAXB * ODIM];
__device__ float  g_OUTT[(size_t)TROWS * ODIM];
__device__ __half g_WThi[(size_t)NLAY * DM * DM + 512 * DM];
__device__ __half g_WTlo[(size_t)NLAY * DM * DM + 512 * DM];

__device__ __forceinline__ uint32_t smem_u32(const void* p) {
    uint32_t a;
    asm("{ .reg .u64 t; cvta.to.shared.u64 t, %1; cvt.u32.u64 %0, t; }" : "=r"(a) : "l"(p));
    return a;
}
#define SWZ(o) ((o) ^ (((o) >> 3) & 0x70))

__device__ __forceinline__ void cp16(uint32_t so, const void* g) {
    asm volatile("cp.async.cg.shared.global [%0], [%1], 16;" :: "r"(so), "l"(g));
}
__device__ __forceinline__ void ldsm4(uint32_t* r, uint32_t addr) {
    asm volatile("ldmatrix.sync.aligned.m8n8.x4.shared.b16 {%0,%1,%2,%3}, [%4];"
                 : "=r"(r[0]), "=r"(r[1]), "=r"(r[2]), "=r"(r[3]) : "r"(addr));
}
__device__ __forceinline__ void mma16816(float* c, const uint32_t* a, uint32_t b0, uint32_t b1) {
    asm volatile("mma.sync.aligned.m16n8k16.row.col.f32.f16.f16.f32 "
                 "{%0,%1,%2,%3}, {%4,%5,%6,%7}, {%8,%9}, {%0,%1,%2,%3};"
                 : "+f"(c[0]), "+f"(c[1]), "+f"(c[2]), "+f"(c[3])
                 : "r"(a[0]), "r"(a[1]), "r"(a[2]), "r"(a[3]), "r"(b0), "r"(b1));
}

__device__ __forceinline__ float sigf(float p) { return 1.0f / (1.0f + expf(-p)); }

__device__ __forceinline__ void store2split(__half* ph, __half* pl, float a, float b) {
    __half2 h;
    h.x = __float2half(a); h.y = __float2half(b);
    __half2 l;
    l.x = __float2half(a - __half2float(h.x));
    l.y = __float2half(b - __half2float(h.y));
    *(__half2*)ph = h;
    *(__half2*)pl = l;
}

__device__ __forceinline__ void store4split(__half* ph, __half* pl, float4 v) {
    __align__(8) __half h[4], l[4];
    float vv[4] = {v.x, v.y, v.z, v.w};
#pragma unroll
    for (int i = 0; i < 4; i++) {
        h[i] = __float2half(vv[i]);
        l[i] = __float2half(vv[i] - __half2float(h[i]));
    }
    *(uint2*)ph = *(uint2*)h;
    *(uint2*)pl = *(uint2*)l;
}

// ------------------ prep: transpose + hi/lo split of weights ----------------
__global__ void prep_transpose(const float* __restrict__ W,
                               __half* __restrict__ Thi,
                               __half* __restrict__ Tlo,
                               int Krows, int Ncols)
{
    __shared__ float t[32][33];
    const float* Wz = W + (size_t)blockIdx.z * Krows * Ncols;
    __half* Hz = Thi + (size_t)blockIdx.z * Ncols * Krows;
    __half* Lz = Tlo + (size_t)blockIdx.z * Ncols * Krows;
    int n0 = blockIdx.x * 32, k0 = blockIdx.y * 32;
    int tx = threadIdx.x, ty = threadIdx.y;
#pragma unroll
    for (int i = 0; i < 4; i++)
        t[ty + 8 * i][tx] = Wz[(size_t)(k0 + ty + 8 * i) * Ncols + n0 + tx];
    __syncthreads();
#pragma unroll
    for (int i = 0; i < 4; i++) {
        int n = n0 + ty + 8 * i;
        float v = t[tx][ty + 8 * i];
        __half h = __float2half(v);
        Hz[(size_t)n * Krows + k0 + tx] = h;
        Lz[(size_t)n * Krows + k0 + tx] = __float2half(v - __half2float(h));
    }
}

// ---------------- layer 0: fused input GEMV + activation -------------------
__global__ void layer0_kernel(const float* __restrict__ x,
                              const float* __restrict__ W0,
                              const float* __restrict__ b0,
                              __half* __restrict__ Ph, __half* __restrict__ Pl,
                              __half* __restrict__ Th, __half* __restrict__ Tl,
                              int B)
{
    int idx = blockIdx.x * blockDim.x + threadIdx.x;
    if (idx >= B * 256) return;
    int b = idx >> 8;
    int c = (idx & 255) * 4;
    float x0 = __ldg(x + b * 4 + 0), x1 = __ldg(x + b * 4 + 1);
    float x2 = __ldg(x + b * 4 + 2), x3 = __ldg(x + b * 4 + 3);
    float4 w0 = *(const float4*)(W0 + c);
    float4 w1 = *(const float4*)(W0 + 1024 + c);
    float4 w2 = *(const float4*)(W0 + 2048 + c);
    float4 w3 = *(const float4*)(W0 + 3072 + c);
    float4 bb = *(const float4*)(b0 + c);
    float p[4], act[4], d[4];
    float wv[4][4] = {{w0.x, w1.x, w2.x, w3.x}, {w0.y, w1.y, w2.y, w3.y},
                      {w0.z, w1.z, w2.z, w3.z}, {w0.w, w1.w, w2.w, w3.w}};
    float bv[4] = {bb.x, bb.y, bb.z, bb.w};
#pragma unroll
    for (int i = 0; i < 4; i++) {
        p[i] = fmaf(x0, wv[i][0], fmaf(x1, wv[i][1], fmaf(x2, wv[i][2], fmaf(x3, wv[i][3], bv[i]))));
        float sg = sigf(p[i]);
        act[i] = p[i] * sg;
        d[i] = sg * fmaf(p[i], 1.0f - sg, 1.0f);
    }
    size_t pb = (size_t)b * DM + c;
    store4split(Ph + pb, Pl + pb, make_float4(act[0], act[1], act[2], act[3]));
#pragma unroll
    for (int j = 0; j < 4; j++) {
        float4 t = make_float4(d[0] * wv[0][j], d[1] * wv[1][j], d[2] * wv[2][j], d[3] * wv[3][j]);
        size_t tb = ((size_t)j * B + b) * DM + c;
        store4split(Th + tb, Tl + tb, t);
    }
}

// ---------------- HMMA GEMM + element-local fused epilogue (R9 core) -------
// modes: 0 primal-hidden (bias+silu, write act + D)
//        1 tangent-hidden (scale by D, write act)
//        2 primal-out (bias, fp32 store)   3 tangent-out (fp32 store)
#define STG 49152
#define NSTAGE 2

__device__ __forceinline__ void load_stage(uint32_t sb,
    const __half* Ah, const __half* Al, const __half* Bh, const __half* Bl,
    int row0, int col0, int k0, int K, int tid)
{
    const __half* gs[4] = {Ah, Al, Bh, Bl};
    const uint32_t po[4] = {0u, 16384u, 32768u, 40960u};
#pragma unroll
    for (int pl = 0; pl < 4; pl++) {
        const __half* g = gs[pl];
        int r0 = (pl < 2) ? row0 : col0;
        int iters = (pl < 2) ? 4 : 2;
        uint32_t pb = sb + po[pl];
#pragma unroll
        for (int it = 0; it < 4; it++) {
            if (it >= iters) break;
            int t = tid + it * 256;
            int r = t >> 3, cc = t & 7;
            cp16(pb + SWZ(r * 128 + cc * 16), g + (size_t)(r0 + r) * K + k0 + cc * 8);
        }
    }
    asm volatile("cp.async.commit_group;" ::: "memory");
}

__global__ void __launch_bounds__(256, 2)
gemm_fused(const __half* __restrict__ Ain, const __half* __restrict__ Alin,
           const __half* __restrict__ Bh, const __half* __restrict__ Bl,
           const float* __restrict__ bias,
           __half* __restrict__ Oh, __half* __restrict__ Ol,
           float* __restrict__ Dbuf, float* __restrict__ C,
           int K, int ldc, int Nstore, int Bn, int mode)
{
    extern __shared__ char smem[];
    uint32_t sbase = smem_u32(smem);
    int tid = threadIdx.x, wid = tid >> 5, lid = tid & 31;
    int wm = wid & 3, wn = wid >> 2;
    int row0 = blockIdx.y * 128;
    int col0 = blockIdx.x * 64;

    float acc[2][4][4];
#pragma unroll
    for (int i = 0; i < 2; i++)
#pragma unroll
        for (int j = 0; j < 4; j++)
#pragma unroll
            for (int q = 0; q < 4; q++) acc[i][j][q] = 0.0f;

    const int KITER = K >> 6;
    load_stage(sbase + 0 * STG, Ain, Alin, Bh, Bl, row0, col0, 0, K, tid);
    load_stage(sbase + 1 * STG, Ain, Alin, Bh, Bl, row0, col0, 64, K, tid);

    int lrow = lid & 15;
    int kadd = (lid & 16) ? 8 : 0;

    for (int i = 0; i < KITER; i++) {
        asm volatile("cp.async.wait_group 1;" ::: "memory");
        __syncthreads();
        uint32_t stg = sbase + (i & 1) * STG;
        uint32_t Abh = stg, Abl = stg + 16384, Bbh = stg + 32768, Bbl = stg + 40960;

#pragma unroll
        for (int ks = 0; ks < 4; ks++) {
            int col = ks * 16 + kadd;
            uint32_t ahi[2][4], alo[2][4], bhi[2][4], blo[2][4];
#pragma unroll
            for (int mi = 0; mi < 2; mi++) {
                uint32_t off = SWZ((wm * 32 + mi * 16 + lrow) * 128 + col * 2);
                ldsm4(ahi[mi], Abh + off);
                ldsm4(alo[mi], Abl + off);
            }
#pragma unroll
            for (int j = 0; j < 2; j++) {
                uint32_t off = SWZ((wn * 32 + j * 16 + lrow) * 128 + col * 2);
                ldsm4(bhi[j], Bbh + off);
                ldsm4(blo[j], Bbl + off);
            }
#pragma unroll
            for (int mi = 0; mi < 2; mi++)
#pragma unroll
                for (int j = 0; j < 2; j++) {
                    mma16816(acc[mi][2 * j],     ahi[mi], bhi[j][0], bhi[j][2]);
                    mma16816(acc[mi][2 * j + 1], ahi[mi], bhi[j][1], bhi[j][3]);
                }
#pragma unroll
            for (int mi = 0; mi < 2; mi++)
#pragma unroll
                for (int j = 0; j < 2; j++) {
                    mma16816(acc[mi][2 * j],     ahi[mi], blo[j][0], blo[j][2]);
                    mma16816(acc[mi][2 * j + 1], ahi[mi], blo[j][1], blo[j][3]);
                }
#pragma unroll
            for (int mi = 0; mi < 2; mi++)
#pragma unroll
                for (int j = 0; j < 2; j++) {
                    mma16816(acc[mi][2 * j],     alo[mi], bhi[j][0], bhi[j][2]);
                    mma16816(acc[mi][2 * j + 1], alo[mi], bhi[j][1], bhi[j][3]);
                }
        }
        __syncthreads();
        if (i + NSTAGE < KITER)
            load_stage(stg, Ain, Alin, Bh, Bl, row0, col0, (i + NSTAGE) * 64, K, tid);
        else
            asm volatile("cp.async.commit_group;" ::: "memory");
    }

    int trow = lid >> 2, tcol = (lid & 3) * 2;
    int jB = (mode == 1 || mode == 3) ? (row0 / Bn) * Bn : 0;

#pragma unroll
    for (int mi = 0; mi < 2; mi++) {
#pragma unroll
        for (int j = 0; j < 4; j++) {
            int gc = col0 + wn * 32 + j * 8 + tcol;
#pragma unroll
            for (int hv = 0; hv < 2; hv++) {
                int gr = row0 + wm * 32 + mi * 16 + trow + hv * 8;
                float a0 = acc[mi][j][2 * hv], a1 = acc[mi][j][2 * hv + 1];
                if (mode == 0) {
                    float p0 = a0 + bias[gc], p1 = a1 + bias[gc + 1];
                    float s0 = sigf(p0), s1 = sigf(p1);
                    size_t o = (size_t)gr * DM + gc;
                    store2split(Oh + o, Ol + o, p0 * s0, p1 * s1);
                    float2 dd;
                    dd.x = s0 * fmaf(p0, 1.0f - s0, 1.0f);
                    dd.y = s1 * fmaf(p1, 1.0f - s1, 1.0f);
                    *(float2*)(Dbuf + o) = dd;
                } else if (mode == 1) {
                    float2 dd = *(const float2*)(Dbuf + (size_t)(gr - jB) * DM + gc);
                    size_t o = (size_t)gr * DM + gc;
                    store2split(Oh + o, Ol + o, a0 * dd.x, a1 * dd.y);
                } else {
                    if (gc < Nstore) {
                        float2 v = make_float2(a0, a1);
                        if (mode == 2) { v.x += bias[gc]; v.y += bias[gc + 1]; }
                        *(float2*)(C + (size_t)gr * ldc + gc) = v;
                    }
                }
            }
        }
    }
}

// ---------------- head: softmax-mixture derivative, warp per point ---------
__global__ void finalize_kernel(const float* __restrict__ OUTP,
                                const float* __restrict__ OUTT,
                                float* __restrict__ y, int B)
{
    int warp = (blockIdx.x * blockDim.x + threadIdx.x) >> 5;
    int lane = threadIdx.x & 31;
    if (warp >= B) return;
    const float* o = OUTP + (size_t)warp * ODIM;

    float l0 = o[lane], l1 = o[lane + 32];
    float m = fmaxf(l0, l1);
#pragma unroll
    for (int s = 16; s; s >>= 1) m = fmaxf(m, __shfl_xor_sync(0xFFFFFFFFu, m, s));
    float e0 = expf(l0 - m), e1 = expf(l1 - m);
    float S = e0 + e1;
#pragma unroll
    for (int s = 16; s; s >>= 1) S += __shfl_xor_sync(0xFFFFFFFFu, S, s);
    float s0 = e0 / S, s1 = e1 / S;

    float v0[6], v1[6];
#pragma unroll
    for (int t = 0; t < 6; t++) {
        v0[t] = o[64 + 6 * lane + t];
        v1[t] = o[64 + 6 * (lane + 32) + t];
    }

    float Dm[4][6];
#pragma unroll
    for (int j = 0; j < 4; j++) {
        const float* tj = OUTT + ((size_t)j * B + warp) * ODIM;
        float g0 = tj[lane], g1 = tj[lane + 32];
        float dot = s0 * g0 + s1 * g1;
#pragma unroll
        for (int s = 16; s; s >>= 1) dot += __shfl_xor_sync(0xFFFFFFFFu, dot, s);
#pragma unroll
        for (int t = 0; t < 6; t++) {
            float dv0 = tj[64 + 6 * lane + t];
            float dv1 = tj[64 + 6 * (lane + 32) + t];
            float val = s0 * fmaf(g0 - dot, v0[t], dv0) + s1 * fmaf(g1 - dot, v1[t], dv1);
#pragma unroll
            for (int s = 16; s; s >>= 1) val += __shfl_xor_sync(0xFFFFFFFFu, val, s);
            Dm[j][t] = val;
        }
    }
    if (lane == 0) {
        float u0 =  Dm[1][0] + Dm[2][1] + Dm[3][2];
        float u1 = -Dm[0][0] + Dm[2][3] + Dm[3][4];
        float u2 = -Dm[0][1] - Dm[1][3] + Dm[3][5];
        float u3 = -Dm[0][2] - Dm[1][4] - Dm[2][5];
        *(float4*)(y + (size_t)warp * 4) = make_float4(u0 * 10.0f, u1, u2, u3);
    }
}

// ---------------------------------------------------------------------------
extern "C" void kernel_launch(void* const* d_in, const int* in_sizes, int n_in,
                              void* d_out, int out_size)
{
    const float* x    = (const float*)d_in[0];
    const float* W0   = (const float*)d_in[1];
    const float* b0   = (const float*)d_in[2];
    const float* Wh   = (const float*)d_in[3];
    const float* bh   = (const float*)d_in[4];
    const float* Wout = (const float*)d_in[5];
    const float* bout = (const float*)d_in[6];
    float* y = (float*)d_out;

    int B = in_sizes[0] / 4;

    __half *P0h, *P0l, *P1h, *P1l, *T0h, *T0l, *T1h, *T1l, *WThi, *WTlo;
    float *D0, *D1, *OUTP, *OUTT;
    cudaGetSymbolAddress((void**)&P0h, g_P0h);
    cudaGetSymbolAddress((void**)&P0l, g_P0l);
    cudaGetSymbolAddress((void**)&P1h, g_P1h);
    cudaGetSymbolAddress((void**)&P1l, g_P1l);
    cudaGetSymbolAddress((void**)&T0h, g_T0h);
    cudaGetSymbolAddress((void**)&T0l, g_T0l);
    cudaGetSymbolAddress((void**)&T1h, g_T1h);
    cudaGetSymbolAddress((void**)&T1l, g_T1l);
    cudaGetSymbolAddress((void**)&D0, g_D0);
    cudaGetSymbolAddress((void**)&D1, g_D1);
    cudaGetSymbolAddress((void**)&OUTP, g_OUTP);
    cudaGetSymbolAddress((void**)&OUTT, g_OUTT);
    cudaGetSymbolAddress((void**)&WThi, g_WThi);
    cudaGetSymbolAddress((void**)&WTlo, g_WTlo);

    static int init_done = 0;
    static cudaStream_t s1;
    static cudaEvent_t evP[NLAY], evT[NLAY], evJoin;
    if (!init_done) {
        cudaFuncSetAttribute(gemm_fused, cudaFuncAttributeMaxDynamicSharedMemorySize,
                             NSTAGE * STG);
        cudaStreamCreateWithFlags(&s1, cudaStreamNonBlocking);
        for (int l = 0; l < NLAY; l++) {
            cudaEventCreateWithFlags(&evP[l], cudaEventDisableTiming);
            cudaEventCreateWithFlags(&evT[l], cudaEventDisableTiming);
        }
        cudaEventCreateWithFlags(&evJoin, cudaEventDisableTiming);
        init_done = 1;
    }

    // s0 = default stream (capture stream); s1 = tangent stream
    prep_transpose<<<dim3(32, 32, NLAY), dim3(32, 8)>>>(Wh, WThi, WTlo, DM, DM);
    prep_transpose<<<dim3(ODIM / 32, 32, 1), dim3(32, 8)>>>(
        Wout, WThi + (size_t)NLAY * DM * DM, WTlo + (size_t)NLAY * DM * DM, DM, ODIM);

    layer0_kernel<<<(B * 256 + 255) / 256, 256>>>(x, W0, b0, P0h, P0l, T0h, T0l, B);

    __half *pch = P0h, *pcl = P0l, *pnh = P1h, *pnl = P1l;
    __half *tch = T0h, *tcl = T0l, *tnh = T1h, *tnl = T1l;

    dim3 gP(DM / 64, B / 128);
    dim3 gT(DM / 64, (4 * B) / 128);
    for (int l = 0; l < NLAY; l++) {
        const __half* wh = WThi + (size_t)l * DM * DM;
        const __half* wl = WTlo + (size_t)l * DM * DM;
        float* Dl = (l & 1) ? D1 : D0;

        // WAR guard: P(l) rewrites D[l&1] last read by T(l-2)
        if (l >= 2) cudaStreamWaitEvent(0, evT[l - 2], 0);
        gemm_fused<<<gP, 256, NSTAGE * STG>>>(pch, pcl, wh, wl,
            bh + (size_t)l * DM, pnh, pnl, Dl, nullptr, DM, 0, 0, B, 0);
        cudaEventRecord(evP[l], 0);

        cudaStreamWaitEvent(s1, evP[l], 0);   // T(l) needs D from P(l)
        gemm_fused<<<gT, 256, NSTAGE * STG, s1>>>(tch, tcl, wh, wl,
            nullptr, tnh, tnl, Dl, nullptr, DM, 0, 0, B, 1);
        cudaEventRecord(evT[l], s1);

        __half* t;
        t = pch; pch = pnh; pnh = t;  t = pcl; pcl = pnl; pnl = t;
        t = tch; tch = tnh; tnh = t;  t = tcl; tcl = tnl; tnl = t;
    }

    const __half* woh = WThi + (size_t)NLAY * DM * DM;
    const __half* wol = WTlo + (size_t)NLAY * DM * DM;
    dim3 gPo(ODIM / 64, B / 128);          // 7 column tiles (N = 448 exactly)
    dim3 gTo(ODIM / 64, (4 * B) / 128);
    gemm_fused<<<gPo, 256, NSTAGE * STG>>>(pch, pcl, woh, wol,
        bout, nullptr, nullptr, nullptr, OUTP, DM, ODIM, ODIM, B, 2);
    gemm_fused<<<gTo, 256, NSTAGE * STG, s1>>>(tch, tcl, woh, wol,
        nullptr, nullptr, nullptr, nullptr, OUTT, DM, ODIM, ODIM, B, 3);
    cudaEventRecord(evJoin, s1);
    cudaStreamWaitEvent(0, evJoin, 0);

    finalize_kernel<<<(B * 32 + 255) / 256, 256>>>(OUTP, OUTT, y, B);
}

// round 15
// speedup vs baseline: 1.1606x; 1.0239x over previous
#include <cuda_runtime.h>
#include <cuda_fp16.h>
#include <math.h>
#include <stdint.h>

// ===========================================================================
// DivFreeNetwork, forward-mode. Primal (B x 1024) and tangent (4B x 1024)
// separate; element-local fused epilogues. R15 = R13 launch structure
// (capture-legal stream forks) + R14 hoisted cp.async addressing
// (stride-32 slot partition; SWZ(o+4096m) = SWZ(o)+4096m).
// GEMM core: BK=64, 4 flat planes, 2-stage, 128x64, 2 CTAs/SM.
// ===========================================================================

#define DM 1024
#define ODIM 448
#define NLAY 4
#define MAXB 65536
#define TROWS (4 * MAXB)

__device__ __half g_P0h[(size_t)MAXB * DM];
__device__ __half g_P0l[(size_t)MAXB * DM];
__device__ __half g_P1h[(size_t)MAXB * DM];
__device__ __half g_P1l[(size_t)MAXB * DM];
__device__ __half g_T0h[(size_t)TROWS * DM];
__device__ __half g_T0l[(size_t)TROWS * DM];
__device__ __half g_T1h[(size_t)TROWS * DM];
__device__ __half g_T1l[(size_t)TROWS * DM];
__device__ float  g_D0[(size_t)MAXB * DM];
__device__ float  g_D1[(size_t)MAXB * DM];
__device__ float  g_OUTP[(size_t)MAXB * ODIM];
__device__ float  g_OUTT[(size_t)TROWS * ODIM];
__device__ __half g_WThi[(size_t)NLAY * DM * DM + 512 * DM];
__device__ __half g_WTlo[(size_t)NLAY * DM * DM + 512 * DM];

__device__ __forceinline__ uint32_t smem_u32(const void* p) {
    uint32_t a;
    asm("{ .reg .u64 t; cvta.to.shared.u64 t, %1; cvt.u32.u64 %0, t; }" : "=r"(a) : "l"(p));
    return a;
}
#define SWZ(o) ((o) ^ (((o) >> 3) & 0x70))

__device__ __forceinline__ void cp16(uint32_t so, const void* g) {
    asm volatile("cp.async.cg.shared.global [%0], [%1], 16;" :: "r"(so), "l"(g));
}
__device__ __forceinline__ void ldsm4(uint32_t* r, uint32_t addr) {
    asm volatile("ldmatrix.sync.aligned.m8n8.x4.shared.b16 {%0,%1,%2,%3}, [%4];"
                 : "=r"(r[0]), "=r"(r[1]), "=r"(r[2]), "=r"(r[3]) : "r"(addr));
}
__device__ __forceinline__ void mma16816(float* c, const uint32_t* a, uint32_t b0, uint32_t b1) {
    asm volatile("mma.sync.aligned.m16n8k16.row.col.f32.f16.f16.f32 "
                 "{%0,%1,%2,%3}, {%4,%5,%6,%7}, {%8,%9}, {%0,%1,%2,%3};"
                 : "+f"(c[0]), "+f"(c[1]), "+f"(c[2]), "+f"(c[3])
                 : "r"(a[0]), "r"(a[1]), "r"(a[2]), "r"(a[3]), "r"(b0), "r"(b1));
}

__device__ __forceinline__ float sigf(float p) { return 1.0f / (1.0f + expf(-p)); }

__device__ __forceinline__ void store2split(__half* ph, __half* pl, float a, float b) {
    __half2 h;
    h.x = __float2half(a); h.y = __float2half(b);
    __half2 l;
    l.x = __float2half(a - __half2float(h.x));
    l.y = __float2half(b - __half2float(h.y));
    *(__half2*)ph = h;
    *(__half2*)pl = l;
}

__device__ __forceinline__ void store4split(__half* ph, __half* pl, float4 v) {
    __align__(8) __half h[4], l[4];
    float vv[4] = {v.x, v.y, v.z, v.w};
#pragma unroll
    for (int i = 0; i < 4; i++) {
        h[i] = __float2half(vv[i]);
        l[i] = __float2half(vv[i] - __half2float(h[i]));
    }
    *(uint2*)ph = *(uint2*)h;
    *(uint2*)pl = *(uint2*)l;
}

// ------------------ prep: transpose + hi/lo split of weights ----------------
__global__ void prep_transpose(const float* __restrict__ W,
                               __half* __restrict__ Thi,
                               __half* __restrict__ Tlo,
                               int Krows, int Ncols)
{
    __shared__ float t[32][33];
    const float* Wz = W + (size_t)blockIdx.z * Krows * Ncols;
    __half* Hz = Thi + (size_t)blockIdx.z * Ncols * Krows;
    __half* Lz = Tlo + (size_t)blockIdx.z * Ncols * Krows;
    int n0 = blockIdx.x * 32, k0 = blockIdx.y * 32;
    int tx = threadIdx.x, ty = threadIdx.y;
#pragma unroll
    for (int i = 0; i < 4; i++)
        t[ty + 8 * i][tx] = Wz[(size_t)(k0 + ty + 8 * i) * Ncols + n0 + tx];
    __syncthreads();
#pragma unroll
    for (int i = 0; i < 4; i++) {
        int n = n0 + ty + 8 * i;
        float v = t[tx][ty + 8 * i];
        __half h = __float2half(v);
        Hz[(size_t)n * Krows + k0 + tx] = h;
        Lz[(size_t)n * Krows + k0 + tx] = __float2half(v - __half2float(h));
    }
}

// ---------------- layer 0: fused input GEMV + activation -------------------
__global__ void layer0_kernel(const float* __restrict__ x,
                              const float* __restrict__ W0,
                              const float* __restrict__ b0,
                              __half* __restrict__ Ph, __half* __restrict__ Pl,
                              __half* __restrict__ Th, __half* __restrict__ Tl,
                              int B)
{
    int idx = blockIdx.x * blockDim.x + threadIdx.x;
    if (idx >= B * 256) return;
    int b = idx >> 8;
    int c = (idx & 255) * 4;
    float x0 = __ldg(x + b * 4 + 0), x1 = __ldg(x + b * 4 + 1);
    float x2 = __ldg(x + b * 4 + 2), x3 = __ldg(x + b * 4 + 3);
    float4 w0 = *(const float4*)(W0 + c);
    float4 w1 = *(const float4*)(W0 + 1024 + c);
    float4 w2 = *(const float4*)(W0 + 2048 + c);
    float4 w3 = *(const float4*)(W0 + 3072 + c);
    float4 bb = *(const float4*)(b0 + c);
    float p[4], act[4], d[4];
    float wv[4][4] = {{w0.x, w1.x, w2.x, w3.x}, {w0.y, w1.y, w2.y, w3.y},
                      {w0.z, w1.z, w2.z, w3.z}, {w0.w, w1.w, w2.w, w3.w}};
    float bv[4] = {bb.x, bb.y, bb.z, bb.w};
#pragma unroll
    for (int i = 0; i < 4; i++) {
        p[i] = fmaf(x0, wv[i][0], fmaf(x1, wv[i][1], fmaf(x2, wv[i][2], fmaf(x3, wv[i][3], bv[i]))));
        float sg = sigf(p[i]);
        act[i] = p[i] * sg;
        d[i] = sg * fmaf(p[i], 1.0f - sg, 1.0f);
    }
    size_t pb = (size_t)b * DM + c;
    store4split(Ph + pb, Pl + pb, make_float4(act[0], act[1], act[2], act[3]));
#pragma unroll
    for (int j = 0; j < 4; j++) {
        float4 t = make_float4(d[0] * wv[0][j], d[1] * wv[1][j], d[2] * wv[2][j], d[3] * wv[3][j]);
        size_t tb = ((size_t)j * B + b) * DM + c;
        store4split(Th + tb, Tl + tb, t);
    }
}

// ---------------- HMMA GEMM + element-local fused epilogue -----------------
// modes: 0 primal-hidden (bias+silu, write act + D)
//        1 tangent-hidden (scale by D, write act)
//        2 primal-out (bias, fp32 store)   3 tangent-out (fp32 store)
#define STG 49152
#define NSTAGE 2

// Hoisted loader: each thread owns (r_base = tid>>3, cc = tid&7).
// A slots: rows r_base + {0,32,64,96}; B slots: rows r_base + {0,32}.
// +32 rows = +4096 smem bytes (swizzle-invariant) = +32*DM global halves.
struct Loader {
    const __half *gah, *gal, *gbh, *gbl;   // base ptrs incl. (r0+r_base)*DM + cc*8
    uint32_t soff;                          // SWZ(r_base*128 + cc*16)
};

__device__ __forceinline__ void load_stage(const Loader& L, uint32_t sb, int k0)
{
#pragma unroll
    for (int m = 0; m < 4; m++) {
        cp16(sb + L.soff + 4096u * m,            L.gah + k0 + 32 * DM * m);
        cp16(sb + 16384u + L.soff + 4096u * m,   L.gal + k0 + 32 * DM * m);
    }
#pragma unroll
    for (int m = 0; m < 2; m++) {
        cp16(sb + 32768u + L.soff + 4096u * m,   L.gbh + k0 + 32 * DM * m);
        cp16(sb + 40960u + L.soff + 4096u * m,   L.gbl + k0 + 32 * DM * m);
    }
    asm volatile("cp.async.commit_group;" ::: "memory");
}

__global__ void __launch_bounds__(256, 2)
gemm_fused(const __half* __restrict__ Ain, const __half* __restrict__ Alin,
           const __half* __restrict__ Bh, const __half* __restrict__ Bl,
           const float* __restrict__ bias,
           __half* __restrict__ Oh, __half* __restrict__ Ol,
           float* __restrict__ Dbuf, float* __restrict__ C,
           int ldc, int Nstore, int Bn, int mode)
{
    extern __shared__ char smem[];
    uint32_t sbase = smem_u32(smem);
    int tid = threadIdx.x, wid = tid >> 5, lid = tid & 31;
    int wm = wid & 3, wn = wid >> 2;
    int row0 = blockIdx.y * 128;
    int col0 = blockIdx.x * 64;

    // hoisted load addressing
    Loader L;
    {
        int r_base = tid >> 3, cc = tid & 7;
        L.gah = Ain  + (size_t)(row0 + r_base) * DM + cc * 8;
        L.gal = Alin + (size_t)(row0 + r_base) * DM + cc * 8;
        L.gbh = Bh   + (size_t)(col0 + r_base) * DM + cc * 8;
        L.gbl = Bl   + (size_t)(col0 + r_base) * DM + cc * 8;
        L.soff = SWZ((uint32_t)(r_base * 128 + cc * 16));
    }

    float acc[2][4][4];
#pragma unroll
    for (int i = 0; i < 2; i++)
#pragma unroll
        for (int j = 0; j < 4; j++)
#pragma unroll
            for (int q = 0; q < 4; q++) acc[i][j][q] = 0.0f;

    const int KITER = DM >> 6;
    load_stage(L, sbase + 0 * STG, 0);
    load_stage(L, sbase + 1 * STG, 64);

    int lrow = lid & 15;
    int kadd = (lid & 16) ? 8 : 0;

    // hoisted LDSM swizzle decomposition
    uint32_t arow[2], amask[2], brow[2], bmask[2];
#pragma unroll
    for (int mi = 0; mi < 2; mi++) {
        uint32_t r = (wm * 32 + mi * 16 + lrow) * 128u;
        arow[mi] = r;
        amask[mi] = (r >> 3) & 0x70u;
    }
#pragma unroll
    for (int j = 0; j < 2; j++) {
        uint32_t r = (wn * 32 + j * 16 + lrow) * 128u;
        brow[j] = r;
        bmask[j] = (r >> 3) & 0x70u;
    }

    for (int i = 0; i < KITER; i++) {
        asm volatile("cp.async.wait_group 1;" ::: "memory");
        __syncthreads();
        uint32_t stg = sbase + (i & 1) * STG;

#pragma unroll
        for (int ks = 0; ks < 4; ks++) {
            uint32_t c2 = ks * 32 + kadd * 2;
            uint32_t ahi[2][4], alo[2][4], bhi[2][4], blo[2][4];
#pragma unroll
            for (int mi = 0; mi < 2; mi++) {
                ldsm4(ahi[mi], stg + arow[mi] + (c2 ^ amask[mi]));
                ldsm4(alo[mi], stg + 16384u + arow[mi] + (c2 ^ amask[mi]));
            }
#pragma unroll
            for (int j = 0; j < 2; j++) {
                ldsm4(bhi[j], stg + 32768u + brow[j] + (c2 ^ bmask[j]));
                ldsm4(blo[j], stg + 40960u + brow[j] + (c2 ^ bmask[j]));
            }
#pragma unroll
            for (int mi = 0; mi < 2; mi++)
#pragma unroll
                for (int j = 0; j < 2; j++) {
                    mma16816(acc[mi][2 * j],     ahi[mi], bhi[j][0], bhi[j][2]);
                    mma16816(acc[mi][2 * j + 1], ahi[mi], bhi[j][1], bhi[j][3]);
                }
#pragma unroll
            for (int mi = 0; mi < 2; mi++)
#pragma unroll
                for (int j = 0; j < 2; j++) {
                    mma16816(acc[mi][2 * j],     ahi[mi], blo[j][0], blo[j][2]);
                    mma16816(acc[mi][2 * j + 1], ahi[mi], blo[j][1], blo[j][3]);
                }
#pragma unroll
            for (int mi = 0; mi < 2; mi++)
#pragma unroll
                for (int j = 0; j < 2; j++) {
                    mma16816(acc[mi][2 * j],     alo[mi], bhi[j][0], bhi[j][2]);
                    mma16816(acc[mi][2 * j + 1], alo[mi], bhi[j][1], bhi[j][3]);
                }
        }
        __syncthreads();
        if (i + NSTAGE < KITER)
            load_stage(L, stg, (i + NSTAGE) * 64);
        else
            asm volatile("cp.async.commit_group;" ::: "memory");
    }

    int trow = lid >> 2, tcol = (lid & 3) * 2;
    int jB = (mode == 1 || mode == 3) ? (row0 / Bn) * Bn : 0;

#pragma unroll
    for (int mi = 0; mi < 2; mi++) {
#pragma unroll
        for (int j = 0; j < 4; j++) {
            int gc = col0 + wn * 32 + j * 8 + tcol;
#pragma unroll
            for (int hv = 0; hv < 2; hv++) {
                int gr = row0 + wm * 32 + mi * 16 + trow + hv * 8;
                float a0 = acc[mi][j][2 * hv], a1 = acc[mi][j][2 * hv + 1];
                if (mode == 0) {
                    float p0 = a0 + bias[gc], p1 = a1 + bias[gc + 1];
                    float s0 = sigf(p0), s1 = sigf(p1);
                    size_t o = (size_t)gr * DM + gc;
                    store2split(Oh + o, Ol + o, p0 * s0, p1 * s1);
                    float2 dd;
                    dd.x = s0 * fmaf(p0, 1.0f - s0, 1.0f);
                    dd.y = s1 * fmaf(p1, 1.0f - s1, 1.0f);
                    *(float2*)(Dbuf + o) = dd;
                } else if (mode == 1) {
                    float2 dd = *(const float2*)(Dbuf + (size_t)(gr - jB) * DM + gc);
                    size_t o = (size_t)gr * DM + gc;
                    store2split(Oh + o, Ol + o, a0 * dd.x, a1 * dd.y);
                } else {
                    if (gc < Nstore) {
                        float2 v = make_float2(a0, a1);
                        if (mode == 2) { v.x += bias[gc]; v.y += bias[gc + 1]; }
                        *(float2*)(C + (size_t)gr * ldc + gc) = v;
                    }
                }
            }
        }
    }
}

// ---------------- head: softmax-mixture derivative, warp per point ---------
__global__ void finalize_kernel(const float* __restrict__ OUTP,
                                const float* __restrict__ OUTT,
                                float* __restrict__ y, int B)
{
    int warp = (blockIdx.x * blockDim.x + threadIdx.x) >> 5;
    int lane = threadIdx.x & 31;
    if (warp >= B) return;
    const float* o = OUTP + (size_t)warp * ODIM;

    float l0 = o[lane], l1 = o[lane + 32];
    float m = fmaxf(l0, l1);
#pragma unroll
    for (int s = 16; s; s >>= 1) m = fmaxf(m, __shfl_xor_sync(0xFFFFFFFFu, m, s));
    float e0 = expf(l0 - m), e1 = expf(l1 - m);
    float S = e0 + e1;
#pragma unroll
    for (int s = 16; s; s >>= 1) S += __shfl_xor_sync(0xFFFFFFFFu, S, s);
    float s0 = e0 / S, s1 = e1 / S;

    float v0[6], v1[6];
#pragma unroll
    for (int t = 0; t < 6; t++) {
        v0[t] = o[64 + 6 * lane + t];
        v1[t] = o[64 + 6 * (lane + 32) + t];
    }

    float Dm[4][6];
#pragma unroll
    for (int j = 0; j < 4; j++) {
        const float* tj = OUTT + ((size_t)j * B + warp) * ODIM;
        float g0 = tj[lane], g1 = tj[lane + 32];
        float dot = s0 * g0 + s1 * g1;
#pragma unroll
        for (int s = 16; s; s >>= 1) dot += __shfl_xor_sync(0xFFFFFFFFu, dot, s);
#pragma unroll
        for (int t = 0; t < 6; t++) {
            float dv0 = tj[64 + 6 * lane + t];
            float dv1 = tj[64 + 6 * (lane + 32) + t];
            float val = s0 * fmaf(g0 - dot, v0[t], dv0) + s1 * fmaf(g1 - dot, v1[t], dv1);
#pragma unroll
            for (int s = 16; s; s >>= 1) val += __shfl_xor_sync(0xFFFFFFFFu, val, s);
            Dm[j][t] = val;
        }
    }
    if (lane == 0) {
        float u0 =  Dm[1][0] + Dm[2][1] + Dm[3][2];
        float u1 = -Dm[0][0] + Dm[2][3] + Dm[3][4];
        float u2 = -Dm[0][1] - Dm[1][3] + Dm[3][5];
        float u3 = -Dm[0][2] - Dm[1][4] - Dm[2][5];
        *(float4*)(y + (size_t)warp * 4) = make_float4(u0 * 10.0f, u1, u2, u3);
    }
}

// ---------------------------------------------------------------------------
extern "C" void kernel_launch(void* const* d_in, const int* in_sizes, int n_in,
                              void* d_out, int out_size)
{
    const float* x    = (const float*)d_in[0];
    const float* W0   = (const float*)d_in[1];
    const float* b0   = (const float*)d_in[2];
    const float* Wh   = (const float*)d_in[3];
    const float* bh   = (const float*)d_in[4];
    const float* Wout = (const float*)d_in[5];
    const float* bout = (const float*)d_in[6];
    float* y = (float*)d_out;

    int B = in_sizes[0] / 4;

    __half *P0h, *P0l, *P1h, *P1l, *T0h, *T0l, *T1h, *T1l, *WThi, *WTlo;
    float *D0, *D1, *OUTP, *OUTT;
    cudaGetSymbolAddress((void**)&P0h, g_P0h);
    cudaGetSymbolAddress((void**)&P0l, g_P0l);
    cudaGetSymbolAddress((void**)&P1h, g_P1h);
    cudaGetSymbolAddress((void**)&P1l, g_P1l);
    cudaGetSymbolAddress((void**)&T0h, g_T0h);
    cudaGetSymbolAddress((void**)&T0l, g_T0l);
    cudaGetSymbolAddress((void**)&T1h, g_T1h);
    cudaGetSymbolAddress((void**)&T1l, g_T1l);
    cudaGetSymbolAddress((void**)&D0, g_D0);
    cudaGetSymbolAddress((void**)&D1, g_D1);
    cudaGetSymbolAddress((void**)&OUTP, g_OUTP);
    cudaGetSymbolAddress((void**)&OUTT, g_OUTT);
    cudaGetSymbolAddress((void**)&WThi, g_WThi);
    cudaGetSymbolAddress((void**)&WTlo, g_WTlo);

    static int init_done = 0;
    static cudaStream_t s1;
    static cudaEvent_t evP[NLAY], evT[NLAY], evJoin;
    if (!init_done) {
        cudaFuncSetAttribute(gemm_fused, cudaFuncAttributeMaxDynamicSharedMemorySize,
                             NSTAGE * STG);
        cudaStreamCreateWithFlags(&s1, cudaStreamNonBlocking);
        for (int l = 0; l < NLAY; l++) {
            cudaEventCreateWithFlags(&evP[l], cudaEventDisableTiming);
            cudaEventCreateWithFlags(&evT[l], cudaEventDisableTiming);
        }
        cudaEventCreateWithFlags(&evJoin, cudaEventDisableTiming);
        init_done = 1;
    }

    // All root work on the capture (default) stream; s1 joins only via
    // events recorded on the capture stream (legal fork pattern).
    prep_transpose<<<dim3(32, 32, NLAY), dim3(32, 8)>>>(Wh, WThi, WTlo, DM, DM);
    prep_transpose<<<dim3(ODIM / 32, 32, 1), dim3(32, 8)>>>(
        Wout, WThi + (size_t)NLAY * DM * DM, WTlo + (size_t)NLAY * DM * DM, DM, ODIM);

    layer0_kernel<<<(B * 256 + 255) / 256, 256>>>(x, W0, b0, P0h, P0l, T0h, T0l, B);

    __half *pch = P0h, *pcl = P0l, *pnh = P1h, *pnl = P1l;
    __half *tch = T0h, *tcl = T0l, *tnh = T1h, *tnl = T1l;

    dim3 gP(DM / 64, B / 128);
    dim3 gT(DM / 64, (4 * B) / 128);
    for (int l = 0; l < NLAY; l++) {
        const __half* wh = WThi + (size_t)l * DM * DM;
        const __half* wl = WTlo + (size_t)l * DM * DM;
        float* Dl = (l & 1) ? D1 : D0;

        // WAR guard: P(l) rewrites D[l&1] last read by T(l-2)
        if (l >= 2) cudaStreamWaitEvent(0, evT[l - 2], 0);
        gemm_fused<<<gP, 256, NSTAGE * STG>>>(pch, pcl, wh, wl,
            bh + (size_t)l * DM, pnh, pnl, Dl, nullptr, 0, 0, B, 0);
        cudaEventRecord(evP[l], 0);

        cudaStreamWaitEvent(s1, evP[l], 0);   // T(l) needs D from P(l)
        gemm_fused<<<gT, 256, NSTAGE * STG, s1>>>(tch, tcl, wh, wl,
            nullptr, tnh, tnl, Dl, nullptr, 0, 0, B, 1);
        cudaEventRecord(evT[l], s1);

        __half* t;
        t = pch; pch = pnh; pnh = t;  t = pcl; pcl = pnl; pnl = t;
        t = tch; tch = tnh; tnh = t;  t = tcl; tcl = tnl; tnl = t;
    }

    const __half* woh = WThi + (size_t)NLAY * DM * DM;
    const __half* wol = WTlo + (size_t)NLAY * DM * DM;
    dim3 gPo(ODIM / 64, B / 128);          // 7 column tiles (N = 448 exactly)
    dim3 gTo(ODIM / 64, (4 * B) / 128);
    gemm_fused<<<gPo, 256, NSTAGE * STG>>>(pch, pcl, woh, wol,
        bout, nullptr, nullptr, nullptr, OUTP, ODIM, ODIM, B, 2);
    gemm_fused<<<gTo, 256, NSTAGE * STG, s1>>>(tch, tcl, woh, wol,
        nullptr, nullptr, nullptr, nullptr, OUTT, ODIM, ODIM, B, 3);
    cudaEventRecord(evJoin, s1);
    cudaStreamWaitEvent(0, evJoin, 0);

    finalize_kernel<<<(B * 32 + 255) / 256, 256>>>(OUTP, OUTT, y, B);
}